// round 11
// baseline (speedup 1.0000x reference)
#include <cuda_runtime.h>
#include <cuda_bf16.h>
#include <cstdint>
#include <math.h>

#define Nn 100000
#define Ee 1600000
#define Hh 128
#define Gg 512
#define TDd 256
#define NTILES 12500   // Ee / 128
#define EK_GRID 296
#define NSB 98         // scan blocks: ceil(100000/1024)

typedef unsigned long long ull;

// Scratch (device globals — no allocation allowed)
__device__ float g_agg[(size_t)Nn * Hh];
__device__ float g_h[(size_t)Nn * Hh];
__device__ float g_mean[Gg * Hh];
__device__ float g_rstd[Gg * Hh];
__device__ float g_gamma[Gg * Hh];
__device__ float g_beta[Gg * Hh];
// sort scratch
__device__ int g_cnt[Nn];
__device__ int g_off[Nn];
__device__ int g_bsum[NSB];
__device__ int g_boff[NSB];
__device__ int g_perm[Ee];
__device__ int g_ssrc[Ee];
__device__ int g_sdst[Ee];

__device__ __forceinline__ float silu_f(float v) {
    return v * (1.0f / (1.0f + __expf(-v)));
}

// ---- packed f32x2 helpers --------------------------------------------------
__device__ __forceinline__ ull pack2(float x, float y) {
    ull r;
    asm("mov.b64 %0, {%1, %2};" : "=l"(r) : "f"(x), "f"(y));
    return r;
}
__device__ __forceinline__ void ffma2(ull& d, ull a, ull b) {
    asm("fma.rn.f32x2 %0, %1, %2, %0;" : "+l"(d) : "l"(a), "l"(b));
}
__device__ __forceinline__ float2 unpack2(ull v) {
    float2 r;
    asm("mov.b64 {%0, %1}, %2;" : "=f"(r.x), "=f"(r.y) : "l"(v));
    return r;
}

// ---- warp-level bf16 mma -----------------------------------------------------
__device__ __forceinline__ void mma_bf16(float* c, const uint32_t* a,
                                         uint32_t b0, uint32_t b1) {
    asm("mma.sync.aligned.m16n8k16.row.col.f32.bf16.bf16.f32 "
        "{%0,%1,%2,%3}, {%4,%5,%6,%7}, {%8,%9}, {%0,%1,%2,%3};"
        : "+f"(c[0]), "+f"(c[1]), "+f"(c[2]), "+f"(c[3])
        : "r"(a[0]), "r"(a[1]), "r"(a[2]), "r"(a[3]), "r"(b0), "r"(b1));
}

__device__ __forceinline__ void cvt8(const float* v, uint4* hi, uint4* lo) {
    uint32_t h[4], l[4];
#pragma unroll
    for (int i = 0; i < 4; ++i) {
        float a = v[2 * i], b = v[2 * i + 1];
        __nv_bfloat16 ha = __float2bfloat16(a), hb = __float2bfloat16(b);
        __nv_bfloat16 la = __float2bfloat16(a - __bfloat162float(ha));
        __nv_bfloat16 lb = __float2bfloat16(b - __bfloat162float(hb));
        h[i] = ((uint32_t)__bfloat16_as_ushort(hb) << 16) | (uint32_t)__bfloat16_as_ushort(ha);
        l[i] = ((uint32_t)__bfloat16_as_ushort(lb) << 16) | (uint32_t)__bfloat16_as_ushort(la);
    }
    *hi = make_uint4(h[0], h[1], h[2], h[3]);
    *lo = make_uint4(l[0], l[1], l[2], l[3]);
}

__device__ __forceinline__ void cvt2(float a, float b, uint32_t* hp, uint32_t* lp) {
    __nv_bfloat16 ha = __float2bfloat16(a), hb = __float2bfloat16(b);
    __nv_bfloat16 la = __float2bfloat16(a - __bfloat162float(ha));
    __nv_bfloat16 lb = __float2bfloat16(b - __bfloat162float(hb));
    *hp = ((uint32_t)__bfloat16_as_ushort(hb) << 16) | (uint32_t)__bfloat16_as_ushort(ha);
    *lp = ((uint32_t)__bfloat16_as_ushort(lb) << 16) | (uint32_t)__bfloat16_as_ushort(la);
}

// Stage a (col n, k-half ks) strip of B/W into FRAGMENT-ORDERED smem.
__device__ __forceinline__ void stage_bfrag(char* fh, char* fl, int n, int ks,
                                            const float* w) {
    uint4 h0, l0, h1, l1;
    cvt8(&w[0], &h0, &l0);
    cvt8(&w[8], &h1, &l1);
    const int nf = n >> 3, g = n & 7;
    uint32_t base = (uint32_t)(nf * 32 + g * 4) * 16 + (uint32_t)ks * 8;
    const uint32_t hw[4] = {h0.x, h0.y, h0.z, h0.w};
    const uint32_t hz[4] = {h1.x, h1.y, h1.z, h1.w};
    const uint32_t lw[4] = {l0.x, l0.y, l0.z, l0.w};
    const uint32_t lz[4] = {l1.x, l1.y, l1.z, l1.w};
#pragma unroll
    for (int t = 0; t < 4; ++t) {
        *(uint2*)(fh + base + t * 16) = make_uint2(hw[t], hz[t]);
        *(uint2*)(fl + base + t * 16) = make_uint2(lw[t], lz[t]);
    }
}

// ---------------------------------------------------------------------------
// sort kernels
// ---------------------------------------------------------------------------
__global__ void zero_kernel() {
    int i = blockIdx.x * 256 + threadIdx.x;
    if (i < Nn) g_cnt[i] = 0;
}

__global__ void hist_kernel(const int* __restrict__ ei) {
    int e = blockIdx.x * 256 + threadIdx.x;   // grid 6250 exact
    atomicAdd(&g_cnt[ei[Ee + e]], 1);
}

__global__ __launch_bounds__(1024) void scanA_kernel() {
    __shared__ int wsum[32];
    const int tid = threadIdx.x;
    const int i = blockIdx.x * 1024 + tid;
    const int lane = tid & 31, wid = tid >> 5;
    int v = (i < Nn) ? g_cnt[i] : 0;
    int s = v;
#pragma unroll
    for (int o = 1; o < 32; o <<= 1) {
        int n = __shfl_up_sync(0xFFFFFFFFu, s, o);
        if (lane >= o) s += n;
    }
    if (lane == 31) wsum[wid] = s;
    __syncthreads();
    if (wid == 0) {
        int ws = wsum[lane];
#pragma unroll
        for (int o = 1; o < 32; o <<= 1) {
            int n = __shfl_up_sync(0xFFFFFFFFu, ws, o);
            if (lane >= o) ws += n;
        }
        wsum[lane] = ws;
    }
    __syncthreads();
    int base = (wid > 0) ? wsum[wid - 1] : 0;
    int incl = base + s;
    if (i < Nn) g_off[i] = incl - v;
    if (tid == 1023) g_bsum[blockIdx.x] = incl;
}

__global__ __launch_bounds__(128) void scanB_kernel() {
    __shared__ int wsum[4];
    const int tid = threadIdx.x;
    const int lane = tid & 31, wid = tid >> 5;
    int v = (tid < NSB) ? g_bsum[tid] : 0;
    int s = v;
#pragma unroll
    for (int o = 1; o < 32; o <<= 1) {
        int n = __shfl_up_sync(0xFFFFFFFFu, s, o);
        if (lane >= o) s += n;
    }
    if (lane == 31) wsum[wid] = s;
    __syncthreads();
    if (tid == 0) {
        int r = 0;
#pragma unroll
        for (int w = 0; w < 4; ++w) { int t = wsum[w]; wsum[w] = r; r += t; }
    }
    __syncthreads();
    if (tid < NSB) g_boff[tid] = wsum[wid] + s - v;
}

__global__ __launch_bounds__(1024) void scanC_kernel() {
    int i = blockIdx.x * 1024 + threadIdx.x;
    if (i < Nn) g_off[i] += g_boff[blockIdx.x];
}

__global__ void scatter_kernel(const int* __restrict__ ei) {
    int e = blockIdx.x * 256 + threadIdx.x;   // grid 6250 exact
    int d = ei[Ee + e];
    int pos = atomicAdd(&g_off[d], 1);
    g_perm[pos] = e;
    g_ssrc[pos] = ei[e];
    g_sdst[pos] = d;
}

// ---------------------------------------------------------------------------
// 1) init: g_agg = x
// ---------------------------------------------------------------------------
__global__ void copy_kernel(const float* __restrict__ x) {
    size_t i = (size_t)blockIdx.x * blockDim.x + threadIdx.x;
    ((float4*)g_agg)[i] = ((const float4*)x)[i];
}

// ---------------------------------------------------------------------------
// 2) edge kernel v3: dst-sorted tiles; mma GEMM; smem-transpose epilogue with
//    per-run combined atomics.
// smem (dynamic):
// ---------------------------------------------------------------------------
#define SBE   0
#define SSRC  512
#define SDST  1024
#define SFBH  1536
#define SFBL  (SFBH + 8192)
#define SUN   (SFBL + 8192)            // union region
#define SAHI  SUN                      // A hi: 10240
#define SALO  (SUN + 10240)            // A lo: 10240
#define SC    SUN                      // C: 128*132*4 = 67584
#define EKSM  (SUN + 67584)            // 85504 bytes

__global__ __launch_bounds__(256, 2) void edge_kernel(
    const float* __restrict__ x,
    const float* __restrict__ ea, const float* __restrict__ We,
    const float* __restrict__ be) {
    extern __shared__ __align__(16) char smem[];
    const int tid = threadIdx.x;
    const int wid = tid >> 5;
    const int lane = tid & 31;

    float* be_s = (float*)(smem + SBE);
    int* src_s = (int*)(smem + SSRC);
    int* dst_s = (int*)(smem + SDST);
    float* Cs = (float*)(smem + SC);

    if (tid < 128) be_s[tid] = be[tid];

    // stage B = We^T hi/lo in fragment order, once per persistent block
    {
        int n = tid >> 1;
        int ks = tid & 1;
        float w[16];
#pragma unroll
        for (int j = 0; j < 16; ++j) w[j] = We[(size_t)(ks * 16 + j) * 128 + n];
        stage_bfrag(smem + SFBH, smem + SFBL, n, ks, w);
    }
    __syncthreads();

    const int g = lane >> 2;
    const int t = lane & 3;
    const int mb = wid * 16;

    for (int tile = blockIdx.x; tile < NTILES; tile += gridDim.x) {
        const int e0 = tile * 128;
        // (loop-start barrier below separates prev combine reads from A writes)

        if (tid < 128) src_s[tid] = g_ssrc[e0 + tid];
        else           dst_s[tid - 128] = g_sdst[e0 + (tid - 128)];

        // stage A = permuted edge_attr tile hi/lo
        {
            int row = tid >> 1;
            int ks = tid & 1;
            int e = g_perm[e0 + row];
            const float* ap = ea + (size_t)e * 32 + ks * 16;
            float v[16];
            *(float4*)&v[0]  = *(const float4*)(ap + 0);
            *(float4*)&v[4]  = *(const float4*)(ap + 4);
            *(float4*)&v[8]  = *(const float4*)(ap + 8);
            *(float4*)&v[12] = *(const float4*)(ap + 12);
            uint4 h0, l0, h1, l1;
            cvt8(&v[0], &h0, &l0);
            cvt8(&v[8], &h1, &l1);
            char* ah = smem + SAHI + row * 80 + ks * 32;
            char* al = smem + SALO + row * 80 + ks * 32;
            *(uint4*)ah = h0;  *(uint4*)(ah + 16) = h1;
            *(uint4*)al = l0;  *(uint4*)(al + 16) = l1;
        }
        __syncthreads();

        uint32_t afh[2][4], afl[2][4];
        {
            const char* Ah = smem + SAHI + (mb + g) * 80 + t * 4;
            const char* Al = smem + SALO + (mb + g) * 80 + t * 4;
#pragma unroll
            for (int ks = 0; ks < 2; ++ks) {
                int o = ks * 32;
                afh[ks][0] = *(const uint32_t*)(Ah + o);
                afh[ks][1] = *(const uint32_t*)(Ah + o + 8 * 80);
                afh[ks][2] = *(const uint32_t*)(Ah + o + 16);
                afh[ks][3] = *(const uint32_t*)(Ah + o + 8 * 80 + 16);
                afl[ks][0] = *(const uint32_t*)(Al + o);
                afl[ks][1] = *(const uint32_t*)(Al + o + 8 * 80);
                afl[ks][2] = *(const uint32_t*)(Al + o + 16);
                afl[ks][3] = *(const uint32_t*)(Al + o + 8 * 80 + 16);
            }
        }
        __syncthreads();   // A reads done before C writes into the union

        float c[16][4];
#pragma unroll
        for (int nf = 0; nf < 16; ++nf) {
            c[nf][0] = 0.f; c[nf][1] = 0.f; c[nf][2] = 0.f; c[nf][3] = 0.f;
        }
#pragma unroll
        for (int nf = 0; nf < 16; ++nf) {
            uint4 BH = *(const uint4*)(smem + SFBH + (uint32_t)(nf * 32 + lane) * 16);
            uint4 BL = *(const uint4*)(smem + SFBL + (uint32_t)(nf * 32 + lane) * 16);
            mma_bf16(c[nf], afh[0], BH.x, BH.y);
            mma_bf16(c[nf], afh[1], BH.z, BH.w);
            mma_bf16(c[nf], afh[0], BL.x, BL.y);
            mma_bf16(c[nf], afh[1], BL.z, BL.w);
            mma_bf16(c[nf], afl[0], BH.x, BH.y);
            mma_bf16(c[nf], afl[1], BH.z, BH.w);
        }

        // C -> smem transpose
#pragma unroll
        for (int nf = 0; nf < 16; ++nf) {
#pragma unroll
            for (int rs = 0; rs < 2; ++rs) {
                const int row = mb + g + rs * 8;
                *(float2*)&Cs[row * 132 + nf * 8 + 2 * t] =
                    make_float2(c[nf][rs * 2], c[nf][rs * 2 + 1]);
            }
        }
        __syncthreads();

        // combine: thread = (col strip cs, edge range er); runs of equal dst
        {
            const int cs = tid & 31;
            const int er = tid >> 5;
            const int col = cs * 4;
            const float4 bv = *(const float4*)&be_s[col];
            float4 acc = make_float4(0.f, 0.f, 0.f, 0.f);
            int dprev = dst_s[er * 16];
#pragma unroll
            for (int i = 0; i < 16; ++i) {
                const int e = er * 16 + i;
                const int d = dst_s[e];
                if (d != dprev) {
                    float* dp = g_agg + (size_t)dprev * 128 + col;
                    asm volatile("red.global.add.v4.f32 [%0], {%1,%2,%3,%4};"
                                 :: "l"(dp), "f"(acc.x), "f"(acc.y), "f"(acc.z), "f"(acc.w)
                                 : "memory");
                    acc = make_float4(0.f, 0.f, 0.f, 0.f);
                    dprev = d;
                }
                const float* xb = x + (size_t)src_s[e] * 128 + col;
                float4 xv = *(const float4*)xb;
                float4 cv = *(const float4*)&Cs[e * 132 + col];
                acc.x += fmaxf(xv.x + cv.x + bv.x, 0.f);
                acc.y += fmaxf(xv.y + cv.y + bv.y, 0.f);
                acc.z += fmaxf(xv.z + cv.z + bv.z, 0.f);
                acc.w += fmaxf(xv.w + cv.w + bv.w, 0.f);
            }
            float* dp = g_agg + (size_t)dprev * 128 + col;
            asm volatile("red.global.add.v4.f32 [%0], {%1,%2,%3,%4};"
                         :: "l"(dp), "f"(acc.x), "f"(acc.y), "f"(acc.z), "f"(acc.w)
                         : "memory");
        }
        __syncthreads();   // combine reads done before next tile's A staging
    }
}

// ---------------------------------------------------------------------------
// 3) fused node MLP (R8 proven version: smem-staged A, frag-ordered W)
// ---------------------------------------------------------------------------
#define MP 272
#define MS_AHI 0
#define MS_ALO 34816
#define MS_WFH 69632
#define MS_WFL 77824
#define MS_B1  86016
#define MS_B2  86528
#define MLP_SMEM 87040

extern "C" __global__ __launch_bounds__(256) void mlp_kernel(
    const float* __restrict__ W1, const float* __restrict__ b1,
    const float* __restrict__ W2, const float* __restrict__ b2) {
    extern __shared__ __align__(16) char msm[];
    const int tid = threadIdx.x;
    const int wid = tid >> 5;
    const int lane = tid & 31;
    const int g = lane >> 2;
    const int t = lane & 3;
    const int q = t >> 1;
    const int odd = t & 1;
    const int mb = wid * 16;
    const int r0 = blockIdx.x * 128;

    float* b1s = (float*)(msm + MS_B1);
    float* b2s = (float*)(msm + MS_B2);
    if (tid < 128) b1s[tid] = b1[tid];
    else           b2s[tid - 128] = b2[tid - 128];

    {
        int row = tid >> 1;
        int half = tid & 1;
        int node = r0 + row;
        const float* ap = g_agg + (size_t)node * 128 + half * 64;
#pragma unroll
        for (int gi = 0; gi < 4; ++gi) {
            float v[16];
            if (node < Nn) {
                *(float4*)&v[0]  = *(const float4*)(ap + gi * 16 + 0);
                *(float4*)&v[4]  = *(const float4*)(ap + gi * 16 + 4);
                *(float4*)&v[8]  = *(const float4*)(ap + gi * 16 + 8);
                *(float4*)&v[12] = *(const float4*)(ap + gi * 16 + 12);
            } else {
#pragma unroll
                for (int j = 0; j < 16; ++j) v[j] = 0.f;
            }
            uint4 h0, l0, h1, l1;
            cvt8(&v[0], &h0, &l0);
            cvt8(&v[8], &h1, &l1);
            uint32_t off = (uint32_t)row * MP + (uint32_t)(half * 64 + gi * 16) * 2;
            *(uint4*)(msm + MS_AHI + off)      = h0;
            *(uint4*)(msm + MS_AHI + off + 16) = h1;
            *(uint4*)(msm + MS_ALO + off)      = l0;
            *(uint4*)(msm + MS_ALO + off + 16) = l1;
        }
    }
    __syncthreads();

    float c[16][4];
#pragma unroll
    for (int nf = 0; nf < 16; ++nf) {
        c[nf][0] = 0.f; c[nf][1] = 0.f; c[nf][2] = 0.f; c[nf][3] = 0.f;
    }

    for (int lyr = 0; lyr < 2; ++lyr) {
        const float* W = (lyr == 0) ? W1 : W2;

        for (int kc = 0; kc < 128; kc += 32) {
            {
                int n = tid >> 1;
                int ks = tid & 1;
                float w[16];
#pragma unroll
                for (int j = 0; j < 16; ++j)
                    w[j] = W[(size_t)(kc + ks * 16 + j) * 128 + n];
                stage_bfrag(msm + MS_WFH, msm + MS_WFL, n, ks, w);
            }
            __syncthreads();

            uint32_t afh[2][4], afl[2][4];
            {
                const char* Ah = msm + MS_AHI + (mb + g) * MP + kc * 2 + t * 4;
                const char* Al = msm + MS_ALO + (mb + g) * MP + kc * 2 + t * 4;
#pragma unroll
                for (int ks = 0; ks < 2; ++ks) {
                    int o = ks * 32;
                    afh[ks][0] = *(const uint32_t*)(Ah + o);
                    afh[ks][1] = *(const uint32_t*)(Ah + o + 8 * MP);
                    afh[ks][2] = *(const uint32_t*)(Ah + o + 16);
                    afh[ks][3] = *(const uint32_t*)(Ah + o + 8 * MP + 16);
                    afl[ks][0] = *(const uint32_t*)(Al + o);
                    afl[ks][1] = *(const uint32_t*)(Al + o + 8 * MP);
                    afl[ks][2] = *(const uint32_t*)(Al + o + 16);
                    afl[ks][3] = *(const uint32_t*)(Al + o + 8 * MP + 16);
                }
            }

#pragma unroll
            for (int nf = 0; nf < 16; ++nf) {
                uint4 BH = *(const uint4*)(msm + MS_WFH + (uint32_t)(nf * 32 + lane) * 16);
                uint4 BL = *(const uint4*)(msm + MS_WFL + (uint32_t)(nf * 32 + lane) * 16);
                mma_bf16(c[nf], afh[0], BH.x, BH.y);
                mma_bf16(c[nf], afh[1], BH.z, BH.w);
                mma_bf16(c[nf], afh[0], BL.x, BL.y);
                mma_bf16(c[nf], afh[1], BL.z, BL.w);
                mma_bf16(c[nf], afl[0], BH.x, BH.y);
                mma_bf16(c[nf], afl[1], BH.z, BH.w);
            }
            __syncthreads();
        }

        if (lyr == 0) {
#pragma unroll
            for (int nf = 0; nf < 16; ++nf) {
#pragma unroll
                for (int rs = 0; rs < 2; ++rs) {
                    int row = mb + g + rs * 8;
                    int col = nf * 8 + 2 * t;
                    float m0 = silu_f(c[nf][rs * 2] + b1s[col]);
                    float m1 = silu_f(c[nf][rs * 2 + 1] + b1s[col + 1]);
                    uint32_t hp, lp;
                    cvt2(m0, m1, &hp, &lp);
                    uint32_t off = (uint32_t)row * MP + (uint32_t)col * 2;
                    *(uint32_t*)(msm + MS_AHI + off) = hp;
                    *(uint32_t*)(msm + MS_ALO + off) = lp;
                    c[nf][rs * 2] = 0.f;
                    c[nf][rs * 2 + 1] = 0.f;
                }
            }
            __syncthreads();
        }
    }

#pragma unroll
    for (int rs = 0; rs < 2; ++rs) {
        const int node = r0 + mb + g + rs * 8;
        float* ob = g_h + (size_t)node * 128;
#pragma unroll
        for (int p = 0; p < 8; ++p) {
            const int nfe = 2 * p, nfo = 2 * p + 1;
            float2 me, mo;
            me.x = c[nfe][rs * 2]; me.y = c[nfe][rs * 2 + 1];
            mo.x = c[nfo][rs * 2]; mo.y = c[nfo][rs * 2 + 1];
            ull send = odd ? pack2(me.x, me.y) : pack2(mo.x, mo.y);
            ull recv = __shfl_xor_sync(0xFFFFFFFFu, send, 1);
            float2 rv = unpack2(recv);
            const int nf = odd ? nfo : nfe;
            float2 lo2 = odd ? rv : me;
            float2 hi2 = odd ? mo : rv;
            const int col = nf * 8 + q * 4;
            if (node < Nn) {
                float4 o;
                o.x = lo2.x + b2s[col + 0];
                o.y = lo2.y + b2s[col + 1];
                o.z = hi2.x + b2s[col + 2];
                o.w = hi2.y + b2s[col + 3];
                *(float4*)(ob + col) = o;
            }
        }
    }
}

// ---------------------------------------------------------------------------
// 4) GraphNorm stats
// ---------------------------------------------------------------------------
__global__ void stats_kernel(const int* __restrict__ batch,
                             const float* __restrict__ ms) {
    __shared__ int bounds[2];
    const int g = blockIdx.x;
    if (threadIdx.x < 2) {
        int target = g + threadIdx.x;
        int lo = 0, hi = Nn;
        while (lo < hi) {
            int mid = (lo + hi) >> 1;
            if (batch[mid] < target) lo = mid + 1; else hi = mid;
        }
        bounds[threadIdx.x] = lo;
    }
    __syncthreads();
    const int s = bounds[0], e = bounds[1];
    const int f = threadIdx.x;

    float sum0 = 0.f, sq0 = 0.f, sum1 = 0.f, sq1 = 0.f;
    float sum2 = 0.f, sq2 = 0.f, sum3 = 0.f, sq3 = 0.f;
    int n = s;
    for (; n + 3 < e; n += 4) {
        float v0 = g_h[(size_t)n * 128 + f];
        float v1 = g_h[(size_t)(n + 1) * 128 + f];
        float v2 = g_h[(size_t)(n + 2) * 128 + f];
        float v3 = g_h[(size_t)(n + 3) * 128 + f];
        sum0 += v0; sq0 += v0 * v0;
        sum1 += v1; sq1 += v1 * v1;
        sum2 += v2; sq2 += v2 * v2;
        sum3 += v3; sq3 += v3 * v3;
    }
    for (; n < e; ++n) {
        float v0 = g_h[(size_t)n * 128 + f];
        sum0 += v0; sq0 += v0 * v0;
    }
    float sum = (sum0 + sum1) + (sum2 + sum3);
    float sq = (sq0 + sq1) + (sq2 + sq3);

    float c = fmaxf((float)(e - s), 1.f);
    float mean = sum / c;
    float m2 = sq / c;
    float msf = ms[f];
    float var = m2 - (2.f * msf - msf * msf) * mean * mean;
    var = fmaxf(var, 0.f);
    g_mean[g * 128 + f] = mean * msf;
    g_rstd[g * 128 + f] = rsqrtf(var + 1e-5f);
}

// ---------------------------------------------------------------------------
// 5) FiLM params: 2 graphs per block (proven config)
// ---------------------------------------------------------------------------
__global__ __launch_bounds__(256) void film_kernel(
    const float* __restrict__ te,
    const float* __restrict__ Wg, const float* __restrict__ bg,
    const float* __restrict__ Wb, const float* __restrict__ bb) {
    __shared__ float tes[256][2];
    const int tid = threadIdx.x;
    const int g0 = blockIdx.x * 2;

    if (tid < 128) {
        int g = tid >> 6, c4 = (tid & 63) * 4;
        float4 v = *(const float4*)&te[(size_t)(g0 + g) * 256 + c4];
        tes[c4 + 0][g] = v.x;
        tes[c4 + 1][g] = v.y;
        tes[c4 + 2][g] = v.z;
        tes[c4 + 3][g] = v.w;
    }
    __syncthreads();

    const int f = tid & 127;
    const int half = tid >> 7;
    const float* W = half ? Wb : Wg;

    ull acc0 = 0ULL, acc1 = 0ULL;
#pragma unroll 8
    for (int k = 0; k < 256; k += 2) {
        float w0 = W[(size_t)k * 128 + f];
        float w1 = W[(size_t)(k + 1) * 128 + f];
        ull t0 = *reinterpret_cast<const ull*>(&tes[k][0]);
        ull t1 = *reinterpret_cast<const ull*>(&tes[k + 1][0]);
        ffma2(acc0, pack2(w0, w0), t0);
        ffma2(acc1, pack2(w1, w1), t1);
    }
    float2 p0 = unpack2(acc0), p1 = unpack2(acc1);
    float add = half ? bb[f] : (bg[f] + 1.0f);
    float* dst = half ? g_beta : g_gamma;
    dst[(g0 + 0) * 128 + f] = p0.x + p1.x + add;
    dst[(g0 + 1) * 128 + f] = p0.y + p1.y + add;
}

// ---------------------------------------------------------------------------
// 6) final elementwise
// ---------------------------------------------------------------------------
__global__ void final_kernel(const float* __restrict__ x,
                             const int* __restrict__ batch,
                             const float* __restrict__ gnw,
                             const float* __restrict__ gnb,
                             float* __restrict__ out) {
    int i = blockIdx.x * blockDim.x + threadIdx.x;
    int n = i >> 5;
    int f4 = (i & 31) * 4;
    int g = batch[n];

    float4 h4 = *(float4*)&g_h[(size_t)n * 128 + f4];
    float4 x4 = *(const float4*)&x[(size_t)n * 128 + f4];
    float4 mn = *(float4*)&g_mean[g * 128 + f4];
    float4 rs = *(float4*)&g_rstd[g * 128 + f4];
    float4 gm = *(float4*)&g_gamma[g * 128 + f4];
    float4 bt = *(float4*)&g_beta[g * 128 + f4];
    float4 w4 = *(const float4*)&gnw[f4];
    float4 b4 = *(const float4*)&gnb[f4];

    float4 o;
    o.x = x4.x + silu_f(gm.x * (w4.x * ((h4.x - mn.x) * rs.x) + b4.x) + bt.x);
    o.y = x4.y + silu_f(gm.y * (w4.y * ((h4.y - mn.y) * rs.y) + b4.y) + bt.y);
    o.z = x4.z + silu_f(gm.z * (w4.z * ((h4.z - mn.z) * rs.z) + b4.z) + bt.z);
    o.w = x4.w + silu_f(gm.w * (w4.w * ((h4.w - mn.w) * rs.w) + b4.w) + bt.w);
    *(float4*)&out[(size_t)n * 128 + f4] = o;
}

// ---------------------------------------------------------------------------
extern "C" void kernel_launch(void* const* d_in, const int* in_sizes, int n_in,
                              void* d_out, int out_size) {
    const float* x   = (const float*)d_in[0];
    const int*   ei  = (const int*)d_in[1];
    const float* ea  = (const float*)d_in[2];
    const int*   bat = (const int*)d_in[3];
    const float* te  = (const float*)d_in[4];
    const float* We  = (const float*)d_in[5];
    const float* be  = (const float*)d_in[6];
    const float* W1  = (const float*)d_in[7];
    const float* b1  = (const float*)d_in[8];
    const float* W2  = (const float*)d_in[9];
    const float* b2  = (const float*)d_in[10];
    const float* gnw = (const float*)d_in[11];
    const float* gnb = (const float*)d_in[12];
    const float* gms = (const float*)d_in[13];
    const float* Wg  = (const float*)d_in[14];
    const float* bg  = (const float*)d_in[15];
    const float* Wb  = (const float*)d_in[16];
    const float* bb  = (const float*)d_in[17];
    float* out = (float*)d_out;

    cudaFuncSetAttribute((const void*)edge_kernel,
                         cudaFuncAttributeMaxDynamicSharedMemorySize, EKSM);
    cudaFuncSetAttribute((const void*)mlp_kernel,
                         cudaFuncAttributeMaxDynamicSharedMemorySize, MLP_SMEM);

    // sort edges by dst
    zero_kernel<<<(Nn + 255) / 256, 256>>>();
    hist_kernel<<<Ee / 256, 256>>>(ei);
    scanA_kernel<<<NSB, 1024>>>();
    scanB_kernel<<<1, 128>>>();
    scanC_kernel<<<NSB, 1024>>>();
    scatter_kernel<<<Ee / 256, 256>>>(ei);

    copy_kernel<<<12500, 256>>>(x);
    edge_kernel<<<EK_GRID, 256, EKSM>>>(x, ea, We, be);
    mlp_kernel<<<(Nn + 127) / 128, 256, MLP_SMEM>>>(W1, b1, W2, b2);
    film_kernel<<<Gg / 2, 256>>>(te, Wg, bg, Wb, bb);
    stats_kernel<<<Gg, 128>>>(bat, gms);
    final_kernel<<<12500, 256>>>(x, bat, gnw, gnb, out);
}